// round 1
// baseline (speedup 1.0000x reference)
#include <cuda_runtime.h>

#define BATCH   64
#define NCLS    80
#define RM      16
#define NO      144      // 80 + 4*16
#define A0      6400     // 80x80
#define A1      1600     // 40x40
#define A2      400      // 20x20
#define AT      8400
#define MAXDET  300

__device__ float g_conf[BATCH * AT];
__device__ int   g_label[BATCH * AT];

// ---------------------------------------------------------------------------
// K1: per-anchor class argmax + sigmoid(max) confidence. Reads ONLY the 80
// class channels (channels 64..143). Coalesced: thread = anchor, loop = channel.
// ---------------------------------------------------------------------------
__global__ void k_conf(const float* __restrict__ f0,
                       const float* __restrict__ f1,
                       const float* __restrict__ f2) {
    int a = blockIdx.x * blockDim.x + threadIdx.x;
    int b = blockIdx.y;
    if (a >= AT) return;

    const float* f; int hw, loc;
    if (a < A0)            { f = f0; hw = A0; loc = a; }
    else if (a < A0 + A1)  { f = f1; hw = A1; loc = a - A0; }
    else                   { f = f2; hw = A2; loc = a - A0 - A1; }

    const float* base = f + ((size_t)b * NO + 4 * RM) * hw + loc;
    float m = base[0];
    int lab = 0;
#pragma unroll 8
    for (int c = 1; c < NCLS; ++c) {
        float v = base[(size_t)c * hw];
        if (v > m) { m = v; lab = c; }   // strict > : first-max, matches argmax
    }
    float conf = 1.0f / (1.0f + __expf(-m));
    g_conf[b * AT + a]  = conf;
    g_label[b * AT + a] = lab;
}

// ---------------------------------------------------------------------------
// K2: one block per batch image.
//   Phase A: top-300 selection (iterative argmax over SMEM conf, 64-bit keys
//            that exactly replicate lax.top_k ordering incl. index tie-break)
//   Phase B: DFL softmax decode of the 300 selected anchors
//   Phase C: greedy class-aware NMS (exact reference op order)
//   Phase D: write (300, 6) rows
// ---------------------------------------------------------------------------
__global__ void __launch_bounds__(1024, 1)
k_select_nms(const float* __restrict__ f0,
             const float* __restrict__ f1,
             const float* __restrict__ f2,
             float* __restrict__ out) {
    __shared__ float s_conf[AT];                       // 33600 B
    __shared__ unsigned long long s_red[32];           // 256 B
    __shared__ int   s_idx[MAXDET];
    __shared__ float s_sc[MAXDET];
    __shared__ float s_lab[MAXDET];
    __shared__ float s_cx[MAXDET], s_cy[MAXDET], s_w[MAXDET], s_h[MAXDET];
    __shared__ float s_x1[MAXDET], s_y1[MAXDET], s_x2[MAXDET], s_y2[MAXDET];
    __shared__ float s_area[MAXDET];
    __shared__ unsigned char s_supp[MAXDET];

    const int b    = blockIdx.x;
    const int tid  = threadIdx.x;
    const int lane = tid & 31;
    const int wid  = tid >> 5;

    for (int i = tid; i < AT; i += 1024)
        s_conf[i] = g_conf[b * AT + i];
    __syncthreads();

    // ---- Phase A: 300 iterations of block-wide argmax ----
    for (int it = 0; it < MAXDET; ++it) {
        unsigned long long best = 0ull;
        for (int i = tid; i < AT; i += 1024) {
            unsigned ub = __float_as_uint(s_conf[i]);
            // monotonic float->uint map (handles the -1.0f "removed" sentinel)
            ub = (ub & 0x80000000u) ? ~ub : (ub | 0x80000000u);
            unsigned long long key =
                ((unsigned long long)ub << 32) | (unsigned)(0xFFFFFFFFu - (unsigned)i);
            if (key > best) best = key;
        }
#pragma unroll
        for (int o = 16; o > 0; o >>= 1) {
            unsigned long long v = __shfl_down_sync(0xFFFFFFFFu, best, o);
            if (v > best) best = v;
        }
        if (lane == 0) s_red[wid] = best;
        __syncthreads();
        if (wid == 0) {
            unsigned long long v = s_red[lane];
#pragma unroll
            for (int o = 16; o > 0; o >>= 1) {
                unsigned long long u = __shfl_down_sync(0xFFFFFFFFu, v, o);
                if (u > v) v = u;
            }
            if (lane == 0) {
                int idx = (int)(0xFFFFFFFFu - (unsigned)(v & 0xFFFFFFFFull));
                s_idx[it] = idx;
                s_sc[it]  = s_conf[idx];
                s_conf[idx] = -1.0f;   // remove from further consideration
            }
        }
        __syncthreads();
    }

    // ---- Phase B: DFL decode for the 300 selected anchors ----
    if (tid < MAXDET) {
        int gidx = s_idx[tid];
        const float* f; int hw, loc, W; float stride;
        if (gidx < A0)           { f = f0; hw = A0; loc = gidx;           W = 80; stride = 8.0f; }
        else if (gidx < A0 + A1) { f = f1; hw = A1; loc = gidx - A0;      W = 40; stride = 16.0f; }
        else                     { f = f2; hw = A2; loc = gidx - A0 - A1; W = 20; stride = 32.0f; }

        const float* p = f + (size_t)b * NO * hw + loc;
        float d[4];
#pragma unroll
        for (int s = 0; s < 4; ++s) {
            float x[RM];
            float m = -1e30f;
#pragma unroll
            for (int k = 0; k < RM; ++k) {
                x[k] = p[(size_t)(s * RM + k) * hw];
                if (x[k] > m) m = x[k];
            }
            float se = 0.0f, sk = 0.0f;
#pragma unroll
            for (int k = 0; k < RM; ++k) {
                float e = __expf(x[k] - m);
                se += e;
                sk += e * (float)k;
            }
            d[s] = sk / se;
        }
        float gx = (float)(loc % W) + 0.5f;
        float gy = (float)(loc / W) + 0.5f;
        float x1 = gx - d[0], y1 = gy - d[1];
        float x2 = gx + d[2], y2 = gy + d[3];
        float cx = (x1 + x2) * 0.5f * stride;
        float cy = (y1 + y2) * 0.5f * stride;
        float w  = (x2 - x1) * stride;
        float h  = (y2 - y1) * stride;
        s_cx[tid] = cx; s_cy[tid] = cy; s_w[tid] = w; s_h[tid] = h;

        float lab = (float)g_label[b * AT + gidx];
        s_lab[tid] = lab;

        // class-offset corner boxes, exact reference op order
        float off = lab * 10000.0f;
        float bx1 = (cx - w * 0.5f) + off;
        float by1 = (cy - h * 0.5f) + off;
        float bx2 = (cx + w * 0.5f) + off;
        float by2 = (cy + h * 0.5f) + off;
        s_x1[tid] = bx1; s_y1[tid] = by1; s_x2[tid] = bx2; s_y2[tid] = by2;
        float aw = bx2 - bx1; if (aw < 0.0f) aw = 0.0f;
        float ah = by2 - by1; if (ah < 0.0f) ah = 0.0f;
        s_area[tid] = aw * ah;

        s_supp[tid] = (s_sc[tid] > 0.001f) ? 0 : 1;  // invalid start suppressed
    }
    __syncthreads();

    // ---- Phase C: greedy NMS (serial over i, parallel over j) ----
    for (int i = 0; i < MAXDET; ++i) {
        if (!s_supp[i] && tid < MAXDET && tid > i) {
            float ix1 = fmaxf(s_x1[i], s_x1[tid]);
            float iy1 = fmaxf(s_y1[i], s_y1[tid]);
            float ix2 = fminf(s_x2[i], s_x2[tid]);
            float iy2 = fminf(s_y2[i], s_y2[tid]);
            float iw = ix2 - ix1; if (iw < 0.0f) iw = 0.0f;
            float ih = iy2 - iy1; if (ih < 0.0f) ih = 0.0f;
            float inter = iw * ih;
            float iou = inter / (s_area[i] + s_area[tid] - inter + 1e-7f);
            if (iou > 0.7f) s_supp[tid] = 1;
        }
        __syncthreads();
    }

    // ---- Phase D: output (300, 6) rows ----
    if (tid < MAXDET) {
        float conf = s_supp[tid] ? 0.0f : s_sc[tid];
        float* o = out + ((size_t)b * MAXDET + tid) * 6;
        o[0] = s_cx[tid];
        o[1] = s_cy[tid];
        o[2] = s_w[tid];
        o[3] = s_h[tid];
        o[4] = conf;
        o[5] = s_lab[tid];
    }
}

extern "C" void kernel_launch(void* const* d_in, const int* in_sizes, int n_in,
                              void* d_out, int out_size) {
    const float* f0 = (const float*)d_in[0];
    const float* f1 = (const float*)d_in[1];
    const float* f2 = (const float*)d_in[2];
    float* out = (float*)d_out;

    dim3 g1((AT + 255) / 256, BATCH);
    k_conf<<<g1, 256>>>(f0, f1, f2);
    k_select_nms<<<BATCH, 1024>>>(f0, f1, f2, out);
}

// round 2
// speedup vs baseline: 3.2769x; 3.2769x over previous
#include <cuda_runtime.h>

#define BATCH   64
#define NCLS    80
#define RM      16
#define NO      144      // 80 + 4*16
#define A0      6400     // 80x80
#define A1      1600     // 40x40
#define A2      400      // 20x20
#define AT      8400
#define MAXDET  300

typedef unsigned long long ull;

__device__ float g_conf[BATCH * AT];
__device__ int   g_label[BATCH * AT];

// ---------------------------------------------------------------------------
// K1: per-anchor class argmax + sigmoid(max). Reads only the 80 class channels.
// ---------------------------------------------------------------------------
__global__ void k_conf(const float* __restrict__ f0,
                       const float* __restrict__ f1,
                       const float* __restrict__ f2) {
    int a = blockIdx.x * blockDim.x + threadIdx.x;
    int b = blockIdx.y;
    if (a >= AT) return;

    const float* f; int hw, loc;
    if (a < A0)            { f = f0; hw = A0; loc = a; }
    else if (a < A0 + A1)  { f = f1; hw = A1; loc = a - A0; }
    else                   { f = f2; hw = A2; loc = a - A0 - A1; }

    const float* base = f + ((size_t)b * NO + 4 * RM) * hw + loc;
    float m = base[0];
    int lab = 0;
#pragma unroll 8
    for (int c = 1; c < NCLS; ++c) {
        float v = base[(size_t)c * hw];
        if (v > m) { m = v; lab = c; }   // strict > : first-max, matches argmax
    }
    float conf = 1.0f / (1.0f + __expf(-m));
    g_conf[b * AT + a]  = conf;
    g_label[b * AT + a] = lab;
}

// ---------------------------------------------------------------------------
// 64-bit key: (monotonic conf bits << 32) | (~index).
// conf = sigmoid(.) > 0, so the monotonic map is just OR of the sign bit.
// Higher conf => bigger key; equal conf => smaller index bigger key.
// Exactly reproduces lax.top_k ordering (descending, index tie-break).
// ---------------------------------------------------------------------------
__device__ __forceinline__ ull make_key(const float* __restrict__ gconf, int i) {
    unsigned ub = __float_as_uint(__ldg(&gconf[i])) | 0x80000000u;
    return ((ull)ub << 32) | (ull)(0xFFFFFFFFu - (unsigned)i);
}

// ---------------------------------------------------------------------------
// K2: one block per batch image.
//   Phase A: exact radix-select of the 300th-largest 64-bit key (8x8-bit passes)
//   Phase A2: compact the 300 winners, bitonic-sort 512 slots descending
//   Phase B: DFL softmax decode of the 300 selected anchors
//   Phase C: greedy class-aware NMS (exact reference op order)
//   Phase D: write (300, 6) rows
// ---------------------------------------------------------------------------
__global__ void __launch_bounds__(1024, 1)
k_select_nms(const float* __restrict__ f0,
             const float* __restrict__ f1,
             const float* __restrict__ f2,
             float* __restrict__ out) {
    __shared__ int  s_hist[256];
    __shared__ ull  s_keys[512];
    __shared__ ull  sh_prefix;
    __shared__ int  sh_rank;
    __shared__ int  s_cnt;
    __shared__ float s_sc[MAXDET];
    __shared__ float s_lab[MAXDET];
    __shared__ float s_cx[MAXDET], s_cy[MAXDET], s_w[MAXDET], s_h[MAXDET];
    __shared__ float s_x1[MAXDET], s_y1[MAXDET], s_x2[MAXDET], s_y2[MAXDET];
    __shared__ float s_area[MAXDET];
    __shared__ unsigned char s_supp[MAXDET];

    const int b    = blockIdx.x;
    const int tid  = threadIdx.x;
    const int lane = tid & 31;
    const int wid  = tid >> 5;
    const float* gconf = g_conf + b * AT;

    if (tid == 0) { sh_prefix = 0ull; sh_rank = MAXDET; s_cnt = 0; }

    // ---- Phase A: radix select (MSB-first, 8 bits/pass) ----
    for (int shift = 56; shift >= 0; shift -= 8) {
        if (tid < 256) s_hist[tid] = 0;
        __syncthreads();
        ull pfx = sh_prefix;
        int hi = shift + 8;
        for (int i = tid; i < AT; i += 1024) {
            ull key = make_key(gconf, i);
            bool active = (hi >= 64) || ((key >> hi) == (pfx >> hi));
            if (active) atomicAdd(&s_hist[(int)((key >> shift) & 255)], 1);
        }
        __syncthreads();
        if (wid == 0) {
            // lane l owns bins [255-8l .. 248-8l] (descending groups of 8)
            int base = 255 - lane * 8;
            int loc[8]; int gs = 0;
#pragma unroll
            for (int t = 0; t < 8; ++t) { loc[t] = s_hist[base - t]; gs += loc[t]; }
            int cum = gs;
#pragma unroll
            for (int o = 1; o < 32; o <<= 1) {
                int v = __shfl_up_sync(0xFFFFFFFFu, cum, o);
                if (lane >= o) cum += v;
            }
            int r = sh_rank;
            bool found = (cum >= r) && ((cum - gs) < r);
            unsigned m = __ballot_sync(0xFFFFFFFFu, found);
            int src = __ffs(m) - 1;
            if (lane == src) {
                int c = cum - gs;
                int d = base;
#pragma unroll
                for (int t = 0; t < 8; ++t) {
                    c += loc[t];
                    if (c >= r) { d = base - t; sh_rank = r - (c - loc[t]); break; }
                }
                sh_prefix = pfx | ((ull)d << shift);
            }
        }
        __syncthreads();
    }

    // ---- Phase A2: collect the 300 keys >= pivot, bitonic sort 512 desc ----
    ull pivot = sh_prefix;
    for (int i = tid; i < AT; i += 1024) {
        ull key = make_key(gconf, i);
        if (key >= pivot) {
            int p = atomicAdd(&s_cnt, 1);
            if (p < 512) s_keys[p] = key;
        }
    }
    if (tid >= MAXDET && tid < 512) s_keys[tid] = 0ull;   // padding (smallest)
    __syncthreads();

#pragma unroll
    for (int k = 2; k <= 512; k <<= 1) {
        for (int j = k >> 1; j > 0; j >>= 1) {
            if (tid < 512) {
                int ixj = tid ^ j;
                if (ixj > tid) {
                    ull a = s_keys[tid], c = s_keys[ixj];
                    bool up = ((tid & k) == 0);          // up-region: descending
                    if (up ? (a < c) : (a > c)) { s_keys[tid] = c; s_keys[ixj] = a; }
                }
            }
            __syncthreads();
        }
    }

    // ---- Phase B: DFL decode for the 300 selected anchors ----
    if (tid < MAXDET) {
        ull key = s_keys[tid];
        int gidx = (int)(0xFFFFFFFFu - (unsigned)(key & 0xFFFFFFFFull));
        float conf = __uint_as_float((unsigned)(key >> 32) & 0x7FFFFFFFu);
        s_sc[tid] = conf;

        const float* f; int hw, loc, W; float stride;
        if (gidx < A0)           { f = f0; hw = A0; loc = gidx;           W = 80; stride = 8.0f; }
        else if (gidx < A0 + A1) { f = f1; hw = A1; loc = gidx - A0;      W = 40; stride = 16.0f; }
        else                     { f = f2; hw = A2; loc = gidx - A0 - A1; W = 20; stride = 32.0f; }

        const float* p = f + (size_t)b * NO * hw + loc;
        float d[4];
#pragma unroll
        for (int s = 0; s < 4; ++s) {
            float x[RM];
            float m = -1e30f;
#pragma unroll
            for (int k = 0; k < RM; ++k) {
                x[k] = p[(size_t)(s * RM + k) * hw];
                if (x[k] > m) m = x[k];
            }
            float se = 0.0f, sk = 0.0f;
#pragma unroll
            for (int k = 0; k < RM; ++k) {
                float e = __expf(x[k] - m);
                se += e;
                sk += e * (float)k;
            }
            d[s] = sk / se;
        }
        float gx = (float)(loc % W) + 0.5f;
        float gy = (float)(loc / W) + 0.5f;
        float x1 = gx - d[0], y1 = gy - d[1];
        float x2 = gx + d[2], y2 = gy + d[3];
        float cx = (x1 + x2) * 0.5f * stride;
        float cy = (y1 + y2) * 0.5f * stride;
        float w  = (x2 - x1) * stride;
        float h  = (y2 - y1) * stride;
        s_cx[tid] = cx; s_cy[tid] = cy; s_w[tid] = w; s_h[tid] = h;

        float lab = (float)__ldg(&g_label[b * AT + gidx]);
        s_lab[tid] = lab;

        float off = lab * 10000.0f;
        float bx1 = (cx - w * 0.5f) + off;
        float by1 = (cy - h * 0.5f) + off;
        float bx2 = (cx + w * 0.5f) + off;
        float by2 = (cy + h * 0.5f) + off;
        s_x1[tid] = bx1; s_y1[tid] = by1; s_x2[tid] = bx2; s_y2[tid] = by2;
        float aw = bx2 - bx1; if (aw < 0.0f) aw = 0.0f;
        float ah = by2 - by1; if (ah < 0.0f) ah = 0.0f;
        s_area[tid] = aw * ah;

        s_supp[tid] = (conf > 0.001f) ? 0 : 1;
    }
    __syncthreads();

    // ---- Phase C: greedy NMS (serial over i, parallel over j) ----
    for (int i = 0; i < MAXDET; ++i) {
        if (!s_supp[i] && tid < MAXDET && tid > i) {
            float ix1 = fmaxf(s_x1[i], s_x1[tid]);
            float iy1 = fmaxf(s_y1[i], s_y1[tid]);
            float ix2 = fminf(s_x2[i], s_x2[tid]);
            float iy2 = fminf(s_y2[i], s_y2[tid]);
            float iw = ix2 - ix1; if (iw < 0.0f) iw = 0.0f;
            float ih = iy2 - iy1; if (ih < 0.0f) ih = 0.0f;
            float inter = iw * ih;
            float iou = inter / (s_area[i] + s_area[tid] - inter + 1e-7f);
            if (iou > 0.7f) s_supp[tid] = 1;
        }
        __syncthreads();
    }

    // ---- Phase D: output (300, 6) rows ----
    if (tid < MAXDET) {
        float conf = s_supp[tid] ? 0.0f : s_sc[tid];
        float* o = out + ((size_t)b * MAXDET + tid) * 6;
        o[0] = s_cx[tid];
        o[1] = s_cy[tid];
        o[2] = s_w[tid];
        o[3] = s_h[tid];
        o[4] = conf;
        o[5] = s_lab[tid];
    }
}

extern "C" void kernel_launch(void* const* d_in, const int* in_sizes, int n_in,
                              void* d_out, int out_size) {
    const float* f0 = (const float*)d_in[0];
    const float* f1 = (const float*)d_in[1];
    const float* f2 = (const float*)d_in[2];
    float* out = (float*)d_out;

    dim3 g1((AT + 255) / 256, BATCH);
    k_conf<<<g1, 256>>>(f0, f1, f2);
    k_select_nms<<<BATCH, 1024>>>(f0, f1, f2, out);
}

// round 3
// speedup vs baseline: 4.6319x; 1.4135x over previous
#include <cuda_runtime.h>

#define BATCH   64
#define NCLS    80
#define RM      16
#define NO      144      // 80 + 4*16
#define A0      6400     // 80x80
#define A1      1600     // 40x40
#define A2      400      // 20x20
#define AT      8400
#define MAXDET  300

typedef unsigned long long ull;

__device__ float g_conf[BATCH * AT];
__device__ int   g_label[BATCH * AT];

// ---------------------------------------------------------------------------
// K1: per-anchor class argmax + sigmoid(max). Reads only the 80 class
// channels, vectorized float4: one thread handles 4 consecutive anchors.
// ---------------------------------------------------------------------------
__global__ void k_conf(const float* __restrict__ f0,
                       const float* __restrict__ f1,
                       const float* __restrict__ f2) {
    int q = blockIdx.x * blockDim.x + threadIdx.x;   // quad index
    int b = blockIdx.y;
    if (q >= AT / 4) return;
    int a = q * 4;

    const float* f; int hw, loc;
    if (a < A0)            { f = f0; hw = A0; loc = a; }
    else if (a < A0 + A1)  { f = f1; hw = A1; loc = a - A0; }
    else                   { f = f2; hw = A2; loc = a - A0 - A1; }

    const float4* base = (const float4*)(f + ((size_t)b * NO + 4 * RM) * hw) + (loc >> 2);
    int hw4 = hw >> 2;

    float4 v = base[0];
    float m0 = v.x, m1 = v.y, m2 = v.z, m3 = v.w;
    int l0 = 0, l1 = 0, l2 = 0, l3 = 0;
#pragma unroll 8
    for (int c = 1; c < NCLS; ++c) {
        v = base[(size_t)c * hw4];
        if (v.x > m0) { m0 = v.x; l0 = c; }
        if (v.y > m1) { m1 = v.y; l1 = c; }
        if (v.z > m2) { m2 = v.z; l2 = c; }
        if (v.w > m3) { m3 = v.w; l3 = c; }
    }
    float4 cf;
    cf.x = 1.0f / (1.0f + __expf(-m0));
    cf.y = 1.0f / (1.0f + __expf(-m1));
    cf.z = 1.0f / (1.0f + __expf(-m2));
    cf.w = 1.0f / (1.0f + __expf(-m3));
    *(float4*)&g_conf[b * AT + a] = cf;
    int4 lb; lb.x = l0; lb.y = l1; lb.z = l2; lb.w = l3;
    *(int4*)&g_label[b * AT + a] = lb;
}

// 64-bit key: (monotonic conf bits << 32) | (~index). conf > 0 so the
// monotonic map is OR of the sign bit. Reproduces lax.top_k ordering exactly.
__device__ __forceinline__ ull make_key(const float* __restrict__ gconf, int i) {
    unsigned ub = __float_as_uint(__ldg(&gconf[i])) | 0x80000000u;
    return ((ull)ub << 32) | (ull)(0xFFFFFFFFu - (unsigned)i);
}

// ---------------------------------------------------------------------------
// K2: one block per batch image.
//   A : radix-select pivot (8x8-bit, warp-aggregated hist, early exit)
//   A2: collect exactly 300 keys >= pivot; rank-by-counting sort
//   B : DFL decode as 1200 (box,side) tasks; box/area/valid setup
//   C : 300x300 IoU adjacency bitmask + single-warp greedy scan
//   D : write (300, 6)
// ---------------------------------------------------------------------------
__global__ void __launch_bounds__(1024, 1)
k_select_nms(const float* __restrict__ f0,
             const float* __restrict__ f1,
             const float* __restrict__ f2,
             float* __restrict__ out) {
    __shared__ int  s_hist[256];
    __shared__ ull  s_keys[MAXDET];
    __shared__ ull  s_skey[MAXDET];
    __shared__ ull  sh_prefix;
    __shared__ int  sh_rank;
    __shared__ int  sh_done;
    __shared__ int  s_cnt;
    __shared__ float s_d[MAXDET][4];
    __shared__ float s_sc[MAXDET];
    __shared__ float s_lab[MAXDET];
    __shared__ float s_cx[MAXDET], s_cy[MAXDET], s_w[MAXDET], s_h[MAXDET];
    __shared__ float s_x1[MAXDET], s_y1[MAXDET], s_x2[MAXDET], s_y2[MAXDET];
    __shared__ float s_area[MAXDET];
    __shared__ unsigned s_adj[MAXDET * 10];   // 300 rows x 10 words
    __shared__ unsigned s_supp[10];

    const int b    = blockIdx.x;
    const int tid  = threadIdx.x;
    const int lane = tid & 31;
    const int wid  = tid >> 5;
    const float* gconf = g_conf + b * AT;

    if (tid == 0) { sh_prefix = 0ull; sh_rank = MAXDET; sh_done = 0; s_cnt = 0; }

    // ---- Phase A: radix select with early exit ----
    for (int shift = 56; shift >= 0; shift -= 8) {
        if (tid < 256) s_hist[tid] = 0;
        __syncthreads();
        ull pfx = sh_prefix;
        int hi = shift + 8;
        for (int base = 0; base < AT; base += 1024) {
            int i = base + tid;
            bool act = false; int bin = 0;
            if (i < AT) {
                ull key = make_key(gconf, i);
                act = (hi >= 64) || ((key >> hi) == (pfx >> hi));
                bin = (int)((key >> shift) & 255);
            }
            unsigned am = __ballot_sync(0xFFFFFFFFu, act);
            if (act) {
                unsigned peers = __match_any_sync(am, bin);
                if ((__ffs(peers) - 1) == lane)
                    atomicAdd(&s_hist[bin], __popc(peers));
            }
        }
        __syncthreads();
        if (wid == 0) {
            int base = 255 - lane * 8;           // lane owns 8 descending bins
            int loc[8]; int gs = 0;
#pragma unroll
            for (int t = 0; t < 8; ++t) { loc[t] = s_hist[base - t]; gs += loc[t]; }
            int cum = gs;
#pragma unroll
            for (int o = 1; o < 32; o <<= 1) {
                int v = __shfl_up_sync(0xFFFFFFFFu, cum, o);
                if (lane >= o) cum += v;
            }
            int r = sh_rank;
            bool found = (cum >= r) && ((cum - gs) < r);
            unsigned m = __ballot_sync(0xFFFFFFFFu, found);
            int src = __ffs(m) - 1;
            if (lane == src) {
                int c = cum - gs;
                int d = base, rr = r, cd = 0;
#pragma unroll
                for (int t = 0; t < 8; ++t) {
                    c += loc[t];
                    if (c >= r) { d = base - t; cd = loc[t]; rr = r - (c - loc[t]); break; }
                }
                sh_rank   = rr;
                sh_prefix = pfx | ((ull)d << shift);
                if (cd == rr) sh_done = 1;       // whole bin selected -> pivot exact
            }
        }
        __syncthreads();
        if (sh_done) break;
    }

    // ---- Phase A2: collect exactly 300 keys >= pivot ----
    ull pivot = sh_prefix;
    for (int i = tid; i < AT; i += 1024) {
        ull key = make_key(gconf, i);
        if (key >= pivot) {
            int p = atomicAdd(&s_cnt, 1);
            if (p < MAXDET) s_keys[p] = key;
        }
    }
    __syncthreads();

    // rank-by-counting (keys are all distinct)
    if (tid < MAXDET) {
        ull k = s_keys[tid];
        int rank = 0;
        for (int j = 0; j < MAXDET; ++j) rank += (s_keys[j] > k);
        s_skey[rank] = k;
    }
    __syncthreads();

    // ---- Phase B: DFL decode as (box, side) tasks ----
    for (int t = tid; t < MAXDET * 4; t += 1024) {
        int box = t >> 2, s = t & 3;
        ull key = s_skey[box];
        int gidx = (int)(0xFFFFFFFFu - (unsigned)(key & 0xFFFFFFFFull));

        const float* f; int hw, loc;
        if (gidx < A0)           { f = f0; hw = A0; loc = gidx; }
        else if (gidx < A0 + A1) { f = f1; hw = A1; loc = gidx - A0; }
        else                     { f = f2; hw = A2; loc = gidx - A0 - A1; }

        const float* p = f + (size_t)b * NO * hw + (size_t)(s * RM) * hw + loc;
        float x[RM];
        float m = -1e30f;
#pragma unroll
        for (int k = 0; k < RM; ++k) {
            x[k] = p[(size_t)k * hw];
            if (x[k] > m) m = x[k];
        }
        float se = 0.0f, sk = 0.0f;
#pragma unroll
        for (int k = 0; k < RM; ++k) {
            float e = __expf(x[k] - m);
            se += e;
            sk += e * (float)k;
        }
        s_d[box][s] = sk / se;
    }
    __syncthreads();

    if (tid < MAXDET) {
        ull key = s_skey[tid];
        int gidx = (int)(0xFFFFFFFFu - (unsigned)(key & 0xFFFFFFFFull));
        float conf = __uint_as_float((unsigned)(key >> 32) & 0x7FFFFFFFu);
        s_sc[tid] = conf;

        int loc, W; float stride;
        if (gidx < A0)           { loc = gidx;           W = 80; stride = 8.0f; }
        else if (gidx < A0 + A1) { loc = gidx - A0;      W = 40; stride = 16.0f; }
        else                     { loc = gidx - A0 - A1; W = 20; stride = 32.0f; }

        float gx = (float)(loc % W) + 0.5f;
        float gy = (float)(loc / W) + 0.5f;
        float x1 = gx - s_d[tid][0], y1 = gy - s_d[tid][1];
        float x2 = gx + s_d[tid][2], y2 = gy + s_d[tid][3];
        float cx = (x1 + x2) * 0.5f * stride;
        float cy = (y1 + y2) * 0.5f * stride;
        float w  = (x2 - x1) * stride;
        float h  = (y2 - y1) * stride;
        s_cx[tid] = cx; s_cy[tid] = cy; s_w[tid] = w; s_h[tid] = h;

        float lab = (float)__ldg(&g_label[b * AT + gidx]);
        s_lab[tid] = lab;

        float off = lab * 10000.0f;
        float bx1 = (cx - w * 0.5f) + off;
        float by1 = (cy - h * 0.5f) + off;
        float bx2 = (cx + w * 0.5f) + off;
        float by2 = (cy + h * 0.5f) + off;
        s_x1[tid] = bx1; s_y1[tid] = by1; s_x2[tid] = bx2; s_y2[tid] = by2;
        float aw = bx2 - bx1; if (aw < 0.0f) aw = 0.0f;
        float ah = by2 - by1; if (ah < 0.0f) ah = 0.0f;
        s_area[tid] = aw * ah;
    }
    __syncthreads();

    // validity (supp-at-start) bitmask: warps 0..9, 32 bits each
    if (tid < 320) {
        bool sup0 = (tid < MAXDET) ? !(s_sc[tid] > 0.001f) : false;
        unsigned wv = __ballot_sync(0xFFFFFFFFu, sup0);
        if (lane == 0) s_supp[tid >> 5] = wv;
    }

    // ---- Phase C: adjacency bitmask (warp per 32-bit word) ----
    for (int t = wid; t < MAXDET * 10; t += 32) {
        int i = t / 10, w = t - i * 10;
        int j = (w << 5) + lane;
        bool p = false;
        if (j < MAXDET && j > i) {
            float ix1 = fmaxf(s_x1[i], s_x1[j]);
            float iy1 = fmaxf(s_y1[i], s_y1[j]);
            float ix2 = fminf(s_x2[i], s_x2[j]);
            float iy2 = fminf(s_y2[i], s_y2[j]);
            float iw = ix2 - ix1; if (iw < 0.0f) iw = 0.0f;
            float ih = iy2 - iy1; if (ih < 0.0f) ih = 0.0f;
            float inter = iw * ih;
            float iou = inter / (s_area[i] + s_area[j] - inter + 1e-7f);
            p = iou > 0.7f;
        }
        unsigned word = __ballot_sync(0xFFFFFFFFu, p);
        if (lane == 0) s_adj[t] = word;
    }
    __syncthreads();

    // greedy scan in one warp: lane w (w<10) holds supp word w in a register
    if (wid == 0) {
        unsigned supp = (lane < 10) ? s_supp[lane] : 0u;
        unsigned row  = (lane < 10) ? s_adj[lane] : 0u;     // row 0 prefetched
        for (int i = 0; i < MAXDET; ++i) {
            unsigned nrow = 0u;
            if (i + 1 < MAXDET && lane < 10) nrow = s_adj[(i + 1) * 10 + lane];
            unsigned sw = __shfl_sync(0xFFFFFFFFu, supp, i >> 5);
            if (!((sw >> (i & 31)) & 1u)) supp |= row;
            row = nrow;
        }
        if (lane < 10) s_supp[lane] = supp;
    }
    __syncthreads();

    // ---- Phase D: output (300, 6) rows ----
    if (tid < MAXDET) {
        bool sup = (s_supp[tid >> 5] >> (lane)) & 1u;
        float conf = sup ? 0.0f : s_sc[tid];
        float* o = out + ((size_t)b * MAXDET + tid) * 6;
        o[0] = s_cx[tid];
        o[1] = s_cy[tid];
        o[2] = s_w[tid];
        o[3] = s_h[tid];
        o[4] = conf;
        o[5] = s_lab[tid];
    }
}

extern "C" void kernel_launch(void* const* d_in, const int* in_sizes, int n_in,
                              void* d_out, int out_size) {
    const float* f0 = (const float*)d_in[0];
    const float* f1 = (const float*)d_in[1];
    const float* f2 = (const float*)d_in[2];
    float* out = (float*)d_out;

    dim3 g1((AT / 4 + 255) / 256, BATCH);
    k_conf<<<g1, 256>>>(f0, f1, f2);
    k_select_nms<<<BATCH, 1024>>>(f0, f1, f2, out);
}